// round 5
// baseline (speedup 1.0000x reference)
#include <cuda_runtime.h>
#include <math.h>

#define BATCH 2
#define SEQ   2000
#define DM    256
#define DI    512
#define DS    16
#define DTR   16
#define NXP   (DTR + 2*DS)   /* 48 */
#define NT    (BATCH*SEQ)    /* 4000 */
#define NL    4

// ---------------- scratch (static device globals; no allocation) ----------------
static __device__ float g_h   [NT*DM];        // residual stream
static __device__ float g_hn  [NT*DM];        // layernormed h
static __device__ float g_xz  [NT*2*DI];      // in_proj output (u | z)
static __device__ float g_u   [NT*DI];        // post-conv + silu
static __device__ float g_xdbc[NT*NXP];       // x_proj output (dt_r | B | C)
static __device__ float g_dt  [NT*DI];        // softplus(dt)
static __device__ float g_y   [NT*DI];        // scan output (gated)

// ---------------- helpers ----------------
__device__ __forceinline__ float blockReduceSum256(float v) {
    __shared__ float sh[8];
    __shared__ float total;
    #pragma unroll
    for (int o = 16; o > 0; o >>= 1) v += __shfl_xor_sync(0xffffffffu, v, o);
    if ((threadIdx.x & 31) == 0) sh[threadIdx.x >> 5] = v;
    __syncthreads();
    if (threadIdx.x == 0) {
        float s = 0.f;
        #pragma unroll
        for (int i = 0; i < 8; i++) s += sh[i];
        total = s;
    }
    __syncthreads();
    return total;
}

// ---------------- kernels ----------------

// h = x[...,None]*w + b + gene_emb + mod_emb
__global__ void embed_kernel(const float* __restrict__ x,
                             const float* __restrict__ w,
                             const float* __restrict__ b,
                             const float* __restrict__ ge,
                             const float* __restrict__ me) {
    int i = blockIdx.x * 256 + threadIdx.x;
    if (i >= NT * DM) return;
    int d = i & (DM - 1);
    int t = i >> 8;
    int l = t % SEQ;
    g_h[i] = x[t] * w[d] + b[d] + ge[l * DM + d] + me[d];
}

// LayerNorm over last dim (256); one block per token
__global__ void ln_kernel(const float* __restrict__ in, float* __restrict__ out,
                          const float* __restrict__ w, const float* __restrict__ b) {
    int t = blockIdx.x, d = threadIdx.x;
    float v = in[t * DM + d];
    float mean = blockReduceSum256(v) * (1.f / DM);
    float diff = v - mean;
    float var = blockReduceSum256(diff * diff) * (1.f / DM);
    out[t * DM + d] = diff * rsqrtf(var + 1e-5f) * w[d] + b[d];
}

// C[M,N] = A[M,K] @ W[N,K]^T  (both K-contiguous), optional accumulate into C.
// 64x64 tile, BK=16, 256 threads, 4x4 micro-tile per thread.
__global__ void sgemm_nt(const float* __restrict__ A, const float* __restrict__ W,
                         float* __restrict__ C, int M, int N, int K, int accum) {
    __shared__ float As[16][68];
    __shared__ float Ws[16][68];
    const int tid = threadIdx.x;
    const int m0 = blockIdx.y * 64, n0 = blockIdx.x * 64;
    const int lr = tid >> 2;            // 0..63
    const int lc = (tid & 3) << 2;      // 0,4,8,12
    const int ty = tid >> 4, tx = tid & 15;
    float acc[4][4];
    #pragma unroll
    for (int i = 0; i < 4; i++)
        #pragma unroll
        for (int j = 0; j < 4; j++) acc[i][j] = 0.f;

    for (int k0 = 0; k0 < K; k0 += 16) {
        int am = m0 + lr;
        float4 av = make_float4(0.f, 0.f, 0.f, 0.f);
        if (am < M) av = *reinterpret_cast<const float4*>(A + (size_t)am * K + k0 + lc);
        int wn = n0 + lr;
        float4 wv = make_float4(0.f, 0.f, 0.f, 0.f);
        if (wn < N) wv = *reinterpret_cast<const float4*>(W + (size_t)wn * K + k0 + lc);
        As[lc + 0][lr] = av.x; As[lc + 1][lr] = av.y; As[lc + 2][lr] = av.z; As[lc + 3][lr] = av.w;
        Ws[lc + 0][lr] = wv.x; Ws[lc + 1][lr] = wv.y; Ws[lc + 2][lr] = wv.z; Ws[lc + 3][lr] = wv.w;
        __syncthreads();
        #pragma unroll
        for (int kk = 0; kk < 16; kk++) {
            float a[4], w[4];
            #pragma unroll
            for (int i = 0; i < 4; i++) a[i] = As[kk][ty * 4 + i];
            #pragma unroll
            for (int j = 0; j < 4; j++) w[j] = Ws[kk][tx * 4 + j];
            #pragma unroll
            for (int i = 0; i < 4; i++)
                #pragma unroll
                for (int j = 0; j < 4; j++)
                    acc[i][j] = fmaf(a[i], w[j], acc[i][j]);
        }
        __syncthreads();
    }
    #pragma unroll
    for (int i = 0; i < 4; i++) {
        int m = m0 + ty * 4 + i;
        if (m >= M) continue;
        #pragma unroll
        for (int j = 0; j < 4; j++) {
            int n = n0 + tx * 4 + j;
            if (n < N) {
                size_t idx = (size_t)m * N + n;
                C[idx] = accum ? (C[idx] + acc[i][j]) : acc[i][j];
            }
        }
    }
}

// Depthwise causal conv (D_CONV=4) over u-half of xz, + bias, + SiLU
__global__ void conv_silu_kernel(const float* __restrict__ cw,
                                 const float* __restrict__ cb) {
    int idx = blockIdx.x * 256 + threadIdx.x;
    if (idx >= NT * DI) return;
    int d = idx & (DI - 1);
    int t = idx >> 9;
    int l = t % SEQ;
    float s = cb[d];
    #pragma unroll
    for (int k = 0; k < 4; k++) {
        int ls = l + k - 3;
        if (ls >= 0) s = fmaf(g_xz[(size_t)(t - l + ls) * (2 * DI) + d], cw[d * 4 + k], s);
    }
    g_u[idx] = s / (1.f + __expf(-s));
}

// xdbc[t, n<48] = sum_k u[t,k] * xpw[n,k]
__global__ void xproj_kernel(const float* __restrict__ xpw) {
    int idx = blockIdx.x * 256 + threadIdx.x;
    if (idx >= NT * NXP) return;
    int n = idx % NXP;
    int t = idx / NXP;
    const float4* ur = reinterpret_cast<const float4*>(g_u + (size_t)t * DI);
    const float4* wr = reinterpret_cast<const float4*>(xpw + (size_t)n * DI);
    float s = 0.f;
    #pragma unroll 4
    for (int k = 0; k < DI / 4; k++) {
        float4 a = ur[k], w = wr[k];
        s += a.x * w.x + a.y * w.y + a.z * w.z + a.w * w.w;
    }
    g_xdbc[idx] = s;
}

// dt[t,d] = softplus( xdbc[t,:16] . dtw[d,:] + dtb[d] )
__global__ void dt_kernel(const float* __restrict__ dtw,
                          const float* __restrict__ dtb) {
    int idx = blockIdx.x * 256 + threadIdx.x;
    if (idx >= NT * DI) return;
    int d = idx & (DI - 1);
    int t = idx >> 9;
    const float* r = g_xdbc + (size_t)t * NXP;
    const float* w = dtw + (size_t)d * DTR;
    float s = dtb[d];
    #pragma unroll
    for (int k = 0; k < DTR; k++) s = fmaf(r[k], w[k], s);
    g_dt[idx] = (s > 20.f) ? s : log1pf(__expf(s));
}

// Selective scan: one thread per (b,d,n). 16-lane shuffle reduction over n.
// Fuses exp(dt*A), recurrence, C-contraction, D skip, and SiLU(z) gating.
__global__ void scan_kernel(const float* __restrict__ A_log,
                            const float* __restrict__ Dv) {
    int gid = blockIdx.x * 256 + threadIdx.x;   // 16384 threads
    int n = gid & 15;
    int g = gid >> 4;        // 0..1023
    int b = g >> 9;
    int d = g & 511;
    const float Ac = -__expf(A_log[d * DS + n]);
    const float Dd = Dv[d];
    float state = 0.f;
    const int tbase = b * SEQ;
    for (int l = 0; l < SEQ; l++) {
        int t = tbase + l;
        float dtv = g_dt[(size_t)t * DI + d];
        float uv  = g_u [(size_t)t * DI + d];
        float Bv  = g_xdbc[(size_t)t * NXP + DTR + n];
        float Cv  = g_xdbc[(size_t)t * NXP + DTR + DS + n];
        float dA = __expf(dtv * Ac);
        state = fmaf(dA, state, dtv * Bv * uv);
        float p = state * Cv;
        p += __shfl_xor_sync(0xffffffffu, p, 1, 16);
        p += __shfl_xor_sync(0xffffffffu, p, 2, 16);
        p += __shfl_xor_sync(0xffffffffu, p, 4, 16);
        p += __shfl_xor_sync(0xffffffffu, p, 8, 16);
        if (n == 0) {
            float z = g_xz[(size_t)t * (2 * DI) + DI + d];
            g_y[(size_t)t * DI + d] = (p + uv * Dd) * (z / (1.f + __expf(-z)));
        }
    }
}

// Final LN + head dot product; one block per token
__global__ void final_kernel(const float* __restrict__ fw, const float* __restrict__ fb,
                             const float* __restrict__ hw, const float* __restrict__ hb,
                             float* __restrict__ out) {
    int t = blockIdx.x, d = threadIdx.x;
    float v = g_h[t * DM + d];
    float mean = blockReduceSum256(v) * (1.f / DM);
    float diff = v - mean;
    float var = blockReduceSum256(diff * diff) * (1.f / DM);
    float nr = diff * rsqrtf(var + 1e-5f) * fw[d] + fb[d];
    float s = blockReduceSum256(nr * hw[d]);
    if (d == 0) out[t] = s + hb[0];
}

// ---------------- launch ----------------
extern "C" void kernel_launch(void* const* d_in, const int* in_sizes, int n_in,
                              void* d_out, int out_size) {
    const float* x         = (const float*)d_in[0];
    const float* bulk_in_w = (const float*)d_in[1];
    const float* bulk_in_b = (const float*)d_in[2];
    const float* gene_emb  = (const float*)d_in[3];
    const float* mod_emb   = (const float*)d_in[4];
    const float* ln_w      = (const float*)d_in[5];
    const float* ln_b      = (const float*)d_in[6];
    const float* in_proj_w = (const float*)d_in[7];
    const float* conv_w    = (const float*)d_in[8];
    const float* conv_b    = (const float*)d_in[9];
    const float* x_proj_w  = (const float*)d_in[10];
    const float* dt_proj_w = (const float*)d_in[11];
    const float* dt_proj_b = (const float*)d_in[12];
    const float* A_log     = (const float*)d_in[13];
    const float* Dvec      = (const float*)d_in[14];
    const float* out_proj_w= (const float*)d_in[15];
    const float* fin_w     = (const float*)d_in[16];
    const float* fin_b     = (const float*)d_in[17];
    const float* head_w    = (const float*)d_in[18];
    const float* head_b    = (const float*)d_in[19];
    float* out = (float*)d_out;

    float *p_h, *p_hn, *p_xz, *p_y;
    cudaGetSymbolAddress((void**)&p_h,  g_h);
    cudaGetSymbolAddress((void**)&p_hn, g_hn);
    cudaGetSymbolAddress((void**)&p_xz, g_xz);
    cudaGetSymbolAddress((void**)&p_y,  g_y);

    embed_kernel<<<(NT * DM + 255) / 256, 256>>>(x, bulk_in_w, bulk_in_b, gene_emb, mod_emb);

    for (int i = 0; i < NL; i++) {
        ln_kernel<<<NT, 256>>>(p_h, p_hn, ln_w + i * DM, ln_b + i * DM);

        // xz = hn @ in_proj_w^T   (M=4000, N=1024, K=256)
        sgemm_nt<<<dim3((2 * DI + 63) / 64, (NT + 63) / 64), 256>>>(
            p_hn, in_proj_w + (size_t)i * (2 * DI) * DM, p_xz, NT, 2 * DI, DM, 0);

        conv_silu_kernel<<<(NT * DI + 255) / 256, 256>>>(conv_w + (size_t)i * DI * 4,
                                                         conv_b + (size_t)i * DI);

        xproj_kernel<<<(NT * NXP + 255) / 256, 256>>>(x_proj_w + (size_t)i * NXP * DI);

        dt_kernel<<<(NT * DI + 255) / 256, 256>>>(dt_proj_w + (size_t)i * DI * DTR,
                                                  dt_proj_b + (size_t)i * DI);

        scan_kernel<<<64, 256>>>(A_log + (size_t)i * DI * DS, Dvec + (size_t)i * DI);

        // h += y @ out_proj_w^T   (M=4000, N=256, K=512)
        sgemm_nt<<<dim3((DM + 63) / 64, (NT + 63) / 64), 256>>>(
            p_y, out_proj_w + (size_t)i * DM * DI, p_h, NT, DM, DI, 1);
    }

    final_kernel<<<NT, 256>>>(fin_w, fin_b, head_w, head_b, out);
}

// round 9
// speedup vs baseline: 3.2265x; 3.2265x over previous
#include <cuda_runtime.h>
#include <math.h>

#define BATCH 2
#define SEQ   2000
#define DM    256
#define DI    512
#define DS    16
#define DTR   16
#define NXP   (DTR + 2*DS)   /* 48 */
#define NT    (BATCH*SEQ)    /* 4000 */
#define NL    4
#define NCHUNK 16
#define CLEN  (SEQ / NCHUNK)  /* 125 */

// ---------------- scratch (static device globals; no allocation) ----------------
static __device__ float g_h   [NT*DM];        // residual stream
static __device__ float g_hn  [NT*DM];        // layernormed h
static __device__ float g_xz  [NT*2*DI];      // in_proj output (u | z)
static __device__ float g_u   [NT*DI];        // post-conv + silu
static __device__ float g_xdbc[NT*NXP];       // x_proj output (dt_r | B | C)
static __device__ float g_dt  [NT*DI];        // softplus(dt)
static __device__ float g_y   [NT*DI];        // scan output (gated)
// chunked-scan carries: [chunk][b][d][n]
static __device__ float g_aprod[NCHUNK*BATCH*DI*DS];
static __device__ float g_send [NCHUNK*BATCH*DI*DS];
static __device__ float g_cin  [NCHUNK*BATCH*DI*DS];

// ---------------- helpers ----------------
__device__ __forceinline__ float blockReduceSum256(float v) {
    __shared__ float sh[8];
    __shared__ float total;
    #pragma unroll
    for (int o = 16; o > 0; o >>= 1) v += __shfl_xor_sync(0xffffffffu, v, o);
    if ((threadIdx.x & 31) == 0) sh[threadIdx.x >> 5] = v;
    __syncthreads();
    if (threadIdx.x == 0) {
        float s = 0.f;
        #pragma unroll
        for (int i = 0; i < 8; i++) s += sh[i];
        total = s;
    }
    __syncthreads();
    return total;
}

// ---------------- kernels ----------------

// h = x[...,None]*w + b + gene_emb + mod_emb
__global__ void embed_kernel(const float* __restrict__ x,
                             const float* __restrict__ w,
                             const float* __restrict__ b,
                             const float* __restrict__ ge,
                             const float* __restrict__ me) {
    int i = blockIdx.x * 256 + threadIdx.x;
    if (i >= NT * DM) return;
    int d = i & (DM - 1);
    int t = i >> 8;
    int l = t % SEQ;
    g_h[i] = x[t] * w[d] + b[d] + ge[l * DM + d] + me[d];
}

// LayerNorm over last dim (256); one block per token
__global__ void ln_kernel(const float* __restrict__ in, float* __restrict__ out,
                          const float* __restrict__ w, const float* __restrict__ b) {
    int t = blockIdx.x, d = threadIdx.x;
    float v = in[t * DM + d];
    float mean = blockReduceSum256(v) * (1.f / DM);
    float diff = v - mean;
    float var = blockReduceSum256(diff * diff) * (1.f / DM);
    out[t * DM + d] = diff * rsqrtf(var + 1e-5f) * w[d] + b[d];
}

// C[M,N] = A[M,K] @ W[N,K]^T  (both K-contiguous), optional accumulate into C.
// 64x64 tile, BK=16, 256 threads, 4x4 micro-tile per thread.
__global__ void sgemm_nt(const float* __restrict__ A, const float* __restrict__ W,
                         float* __restrict__ C, int M, int N, int K, int accum) {
    __shared__ float As[16][68];
    __shared__ float Ws[16][68];
    const int tid = threadIdx.x;
    const int m0 = blockIdx.y * 64, n0 = blockIdx.x * 64;
    const int lr = tid >> 2;            // 0..63
    const int lc = (tid & 3) << 2;      // 0,4,8,12
    const int ty = tid >> 4, tx = tid & 15;
    float acc[4][4];
    #pragma unroll
    for (int i = 0; i < 4; i++)
        #pragma unroll
        for (int j = 0; j < 4; j++) acc[i][j] = 0.f;

    for (int k0 = 0; k0 < K; k0 += 16) {
        int am = m0 + lr;
        float4 av = make_float4(0.f, 0.f, 0.f, 0.f);
        if (am < M) av = *reinterpret_cast<const float4*>(A + (size_t)am * K + k0 + lc);
        int wn = n0 + lr;
        float4 wv = make_float4(0.f, 0.f, 0.f, 0.f);
        if (wn < N) wv = *reinterpret_cast<const float4*>(W + (size_t)wn * K + k0 + lc);
        As[lc + 0][lr] = av.x; As[lc + 1][lr] = av.y; As[lc + 2][lr] = av.z; As[lc + 3][lr] = av.w;
        Ws[lc + 0][lr] = wv.x; Ws[lc + 1][lr] = wv.y; Ws[lc + 2][lr] = wv.z; Ws[lc + 3][lr] = wv.w;
        __syncthreads();
        #pragma unroll
        for (int kk = 0; kk < 16; kk++) {
            float a[4], w[4];
            #pragma unroll
            for (int i = 0; i < 4; i++) a[i] = As[kk][ty * 4 + i];
            #pragma unroll
            for (int j = 0; j < 4; j++) w[j] = Ws[kk][tx * 4 + j];
            #pragma unroll
            for (int i = 0; i < 4; i++)
                #pragma unroll
                for (int j = 0; j < 4; j++)
                    acc[i][j] = fmaf(a[i], w[j], acc[i][j]);
        }
        __syncthreads();
    }
    #pragma unroll
    for (int i = 0; i < 4; i++) {
        int m = m0 + ty * 4 + i;
        if (m >= M) continue;
        #pragma unroll
        for (int j = 0; j < 4; j++) {
            int n = n0 + tx * 4 + j;
            if (n < N) {
                size_t idx = (size_t)m * N + n;
                C[idx] = accum ? (C[idx] + acc[i][j]) : acc[i][j];
            }
        }
    }
}

// Depthwise causal conv (D_CONV=4) over u-half of xz, + bias, + SiLU
__global__ void conv_silu_kernel(const float* __restrict__ cw,
                                 const float* __restrict__ cb) {
    int idx = blockIdx.x * 256 + threadIdx.x;
    if (idx >= NT * DI) return;
    int d = idx & (DI - 1);
    int t = idx >> 9;
    int l = t % SEQ;
    float s = cb[d];
    #pragma unroll
    for (int k = 0; k < 4; k++) {
        int ls = l + k - 3;
        if (ls >= 0) s = fmaf(g_xz[(size_t)(t - l + ls) * (2 * DI) + d], cw[d * 4 + k], s);
    }
    g_u[idx] = s / (1.f + __expf(-s));
}

// xdbc[t, n<48] = sum_k u[t,k] * xpw[n,k]
__global__ void xproj_kernel(const float* __restrict__ xpw) {
    int idx = blockIdx.x * 256 + threadIdx.x;
    if (idx >= NT * NXP) return;
    int n = idx % NXP;
    int t = idx / NXP;
    const float4* ur = reinterpret_cast<const float4*>(g_u + (size_t)t * DI);
    const float4* wr = reinterpret_cast<const float4*>(xpw + (size_t)n * DI);
    float s = 0.f;
    #pragma unroll 4
    for (int k = 0; k < DI / 4; k++) {
        float4 a = ur[k], w = wr[k];
        s += a.x * w.x + a.y * w.y + a.z * w.z + a.w * w.w;
    }
    g_xdbc[idx] = s;
}

// dt[t,d] = softplus( xdbc[t,:16] . dtw[d,:] + dtb[d] )
__global__ void dt_kernel(const float* __restrict__ dtw,
                          const float* __restrict__ dtb) {
    int idx = blockIdx.x * 256 + threadIdx.x;
    if (idx >= NT * DI) return;
    int d = idx & (DI - 1);
    int t = idx >> 9;
    const float* r = g_xdbc + (size_t)t * NXP;
    const float* w = dtw + (size_t)d * DTR;
    float s = dtb[d];
    #pragma unroll
    for (int k = 0; k < DTR; k++) s = fmaf(r[k], w[k], s);
    g_dt[idx] = (s > 20.f) ? s : log1pf(__expf(s));
}

// ---- chunked selective scan ----
// Thread map (pass1/pass2): gid -> n = gid&15, d, b, chunk c. 16 chunks of 125.
// Pass 1: per chunk compute (prod dA, local scan end) with zero initial state.
__global__ void scan_pass1(const float* __restrict__ A_log) {
    int gid = blockIdx.x * 256 + threadIdx.x;   // 262144 threads
    int n = gid & 15;
    int r = gid >> 4;
    int d = r & (DI - 1);
    int b = (r >> 9) & (BATCH - 1);
    int c = r >> 10;
    const float Ac = -__expf(A_log[d * DS + n]);
    float state = 0.f, aprod = 1.f;
    const int t0 = b * SEQ + c * CLEN;
    #pragma unroll 5
    for (int l = 0; l < CLEN; l++) {
        int t = t0 + l;
        float dtv = g_dt[(size_t)t * DI + d];
        float uv  = g_u [(size_t)t * DI + d];
        float Bv  = g_xdbc[(size_t)t * NXP + DTR + n];
        float dA = __expf(dtv * Ac);
        aprod *= dA;
        state = fmaf(dA, state, dtv * Bv * uv);
    }
    int idx = ((c * BATCH + b) * DI + d) * DS + n;
    g_aprod[idx] = aprod;
    g_send[idx]  = state;
}

// Pass 2: serial prefix over the 16 chunks per (b,d,n) -> carry-in per chunk.
__global__ void scan_carry() {
    int gid = blockIdx.x * 256 + threadIdx.x;   // 16384 threads
    int n = gid & 15;
    int d = (gid >> 4) & (DI - 1);
    int b = gid >> 13;
    float carry = 0.f;
    #pragma unroll
    for (int c = 0; c < NCHUNK; c++) {
        int idx = ((c * BATCH + b) * DI + d) * DS + n;
        g_cin[idx] = carry;
        carry = fmaf(g_aprod[idx], carry, g_send[idx]);
    }
}

// Pass 3: rescan each chunk from its carry-in, emit gated output.
__global__ void scan_pass2(const float* __restrict__ A_log,
                           const float* __restrict__ Dv) {
    int gid = blockIdx.x * 256 + threadIdx.x;   // 262144 threads
    int n = gid & 15;
    int r = gid >> 4;
    int d = r & (DI - 1);
    int b = (r >> 9) & (BATCH - 1);
    int c = r >> 10;
    const float Ac = -__expf(A_log[d * DS + n]);
    const float Dd = Dv[d];
    float state = g_cin[((c * BATCH + b) * DI + d) * DS + n];
    const int t0 = b * SEQ + c * CLEN;
    #pragma unroll 5
    for (int l = 0; l < CLEN; l++) {
        int t = t0 + l;
        float dtv = g_dt[(size_t)t * DI + d];
        float uv  = g_u [(size_t)t * DI + d];
        float Bv  = g_xdbc[(size_t)t * NXP + DTR + n];
        float Cv  = g_xdbc[(size_t)t * NXP + DTR + DS + n];
        float dA = __expf(dtv * Ac);
        state = fmaf(dA, state, dtv * Bv * uv);
        float p = state * Cv;
        p += __shfl_xor_sync(0xffffffffu, p, 1, 16);
        p += __shfl_xor_sync(0xffffffffu, p, 2, 16);
        p += __shfl_xor_sync(0xffffffffu, p, 4, 16);
        p += __shfl_xor_sync(0xffffffffu, p, 8, 16);
        if (n == 0) {
            float z = g_xz[(size_t)t * (2 * DI) + DI + d];
            g_y[(size_t)t * DI + d] = (p + uv * Dd) * (z / (1.f + __expf(-z)));
        }
    }
}

// Final LN + head dot product; one block per token
__global__ void final_kernel(const float* __restrict__ fw, const float* __restrict__ fb,
                             const float* __restrict__ hw, const float* __restrict__ hb,
                             float* __restrict__ out) {
    int t = blockIdx.x, d = threadIdx.x;
    float v = g_h[t * DM + d];
    float mean = blockReduceSum256(v) * (1.f / DM);
    float diff = v - mean;
    float var = blockReduceSum256(diff * diff) * (1.f / DM);
    float nr = diff * rsqrtf(var + 1e-5f) * fw[d] + fb[d];
    float s = blockReduceSum256(nr * hw[d]);
    if (d == 0) out[t] = s + hb[0];
}

// ---------------- launch ----------------
extern "C" void kernel_launch(void* const* d_in, const int* in_sizes, int n_in,
                              void* d_out, int out_size) {
    const float* x         = (const float*)d_in[0];
    const float* bulk_in_w = (const float*)d_in[1];
    const float* bulk_in_b = (const float*)d_in[2];
    const float* gene_emb  = (const float*)d_in[3];
    const float* mod_emb   = (const float*)d_in[4];
    const float* ln_w      = (const float*)d_in[5];
    const float* ln_b      = (const float*)d_in[6];
    const float* in_proj_w = (const float*)d_in[7];
    const float* conv_w    = (const float*)d_in[8];
    const float* conv_b    = (const float*)d_in[9];
    const float* x_proj_w  = (const float*)d_in[10];
    const float* dt_proj_w = (const float*)d_in[11];
    const float* dt_proj_b = (const float*)d_in[12];
    const float* A_log     = (const float*)d_in[13];
    const float* Dvec      = (const float*)d_in[14];
    const float* out_proj_w= (const float*)d_in[15];
    const float* fin_w     = (const float*)d_in[16];
    const float* fin_b     = (const float*)d_in[17];
    const float* head_w    = (const float*)d_in[18];
    const float* head_b    = (const float*)d_in[19];
    float* out = (float*)d_out;

    float *p_h, *p_hn, *p_xz, *p_y;
    cudaGetSymbolAddress((void**)&p_h,  g_h);
    cudaGetSymbolAddress((void**)&p_hn, g_hn);
    cudaGetSymbolAddress((void**)&p_xz, g_xz);
    cudaGetSymbolAddress((void**)&p_y,  g_y);

    embed_kernel<<<(NT * DM + 255) / 256, 256>>>(x, bulk_in_w, bulk_in_b, gene_emb, mod_emb);

    for (int i = 0; i < NL; i++) {
        ln_kernel<<<NT, 256>>>(p_h, p_hn, ln_w + i * DM, ln_b + i * DM);

        // xz = hn @ in_proj_w^T   (M=4000, N=1024, K=256)
        sgemm_nt<<<dim3((2 * DI + 63) / 64, (NT + 63) / 64), 256>>>(
            p_hn, in_proj_w + (size_t)i * (2 * DI) * DM, p_xz, NT, 2 * DI, DM, 0);

        conv_silu_kernel<<<(NT * DI + 255) / 256, 256>>>(conv_w + (size_t)i * DI * 4,
                                                         conv_b + (size_t)i * DI);

        xproj_kernel<<<(NT * NXP + 255) / 256, 256>>>(x_proj_w + (size_t)i * NXP * DI);

        dt_kernel<<<(NT * DI + 255) / 256, 256>>>(dt_proj_w + (size_t)i * DI * DTR,
                                                  dt_proj_b + (size_t)i * DI);

        scan_pass1<<<(BATCH * DI * DS * NCHUNK) / 256, 256>>>(A_log + (size_t)i * DI * DS);
        scan_carry<<<(BATCH * DI * DS) / 256, 256>>>();
        scan_pass2<<<(BATCH * DI * DS * NCHUNK) / 256, 256>>>(A_log + (size_t)i * DI * DS,
                                                              Dvec + (size_t)i * DI);

        // h += y @ out_proj_w^T   (M=4000, N=256, K=512)
        sgemm_nt<<<dim3((DM + 63) / 64, (NT + 63) / 64), 256>>>(
            p_y, out_proj_w + (size_t)i * DM * DI, p_h, NT, DM, DI, 1);
    }

    final_kernel<<<NT, 256>>>(fin_w, fin_b, head_w, head_b, out);
}